// round 1
// baseline (speedup 1.0000x reference)
#include <cuda_runtime.h>
#include <math.h>
#include <float.h>

#define NTHREADS 1024
#define MAXN 4096

// Replicates the reference's per-element float32 computation:
//   avg  = s / 200.0
//   sig  = sqrt(-2 / log(1 - avg^2))
//   sig2 = sig^2            (sqrt-then-square, as in reference!)
__device__ __forceinline__ float sig2_of_sum(float s) {
    float avg = s / 200.0f;
    float l   = logf(1.0f - avg * avg);
    float v   = -2.0f / l;
    float sg  = sqrtf(v);
    return sg * sg;
}

__global__ __launch_bounds__(NTHREADS, 1)
void ENCELDDT_67602785239182_kernel(const float* __restrict__ sigmas,
                                    const float* __restrict__ y,
                                    const float* __restrict__ py,
                                    float* __restrict__ out,
                                    int N)
{
    __shared__ float s_sig[MAXN];
    __shared__ int   s_cand[MAXN];
    __shared__ float red_m1[32], red_m2[32], red_M1[32], red_M2[32];
    __shared__ float r_cnt[32], r_ss[32], r_st[32];
    __shared__ float s_begin, s_interval, s_sigth;
    __shared__ int   s_count;

    const int tid = threadIdx.x;
    const unsigned FULL = 0xFFFFFFFFu;

    // ---- Phase A: load sigmas to smem; track 2 smallest + 2 largest ----
    float m1 = FLT_MAX,  m2 = FLT_MAX;
    float M1 = -FLT_MAX, M2 = -FLT_MAX;
    for (int i = tid; i < N; i += NTHREADS) {
        float v = sigmas[i];
        s_sig[i] = v;
        if (v < m1) { m2 = m1; m1 = v; } else if (v < m2) { m2 = v; }
        if (v > M1) { M2 = M1; M1 = v; } else if (v > M2) { M2 = v; }
    }
    // warp reduce (merge (m1,m2)/(M1,M2) pairs)
    #pragma unroll
    for (int off = 16; off; off >>= 1) {
        float a = __shfl_down_sync(FULL, m1, off);
        float b = __shfl_down_sync(FULL, m2, off);
        if (a < m1) { m2 = m1; m1 = a; } else if (a < m2) { m2 = a; }
        if (b < m1) { m2 = m1; m1 = b; } else if (b < m2) { m2 = b; }
        float c = __shfl_down_sync(FULL, M1, off);
        float d = __shfl_down_sync(FULL, M2, off);
        if (c > M1) { M2 = M1; M1 = c; } else if (c > M2) { M2 = c; }
        if (d > M1) { M2 = M1; M1 = d; } else if (d > M2) { M2 = d; }
    }
    if ((tid & 31) == 0) {
        red_m1[tid >> 5] = m1; red_m2[tid >> 5] = m2;
        red_M1[tid >> 5] = M1; red_M2[tid >> 5] = M2;
    }
    __syncthreads();
    if (tid < 32) {
        m1 = red_m1[tid]; m2 = red_m2[tid];
        M1 = red_M1[tid]; M2 = red_M2[tid];
        #pragma unroll
        for (int off = 16; off; off >>= 1) {
            float a = __shfl_down_sync(FULL, m1, off);
            float b = __shfl_down_sync(FULL, m2, off);
            if (a < m1) { m2 = m1; m1 = a; } else if (a < m2) { m2 = a; }
            if (b < m1) { m2 = m1; m1 = b; } else if (b < m2) { m2 = b; }
            float c = __shfl_down_sync(FULL, M1, off);
            float d = __shfl_down_sync(FULL, M2, off);
            if (c > M1) { M2 = M1; M1 = c; } else if (c > M2) { M2 = c; }
            if (d > M1) { M2 = M1; M1 = d; } else if (d > M2) { M2 = d; }
        }
        if (tid == 0) {
            // Off-diagonal min/max sums: fadd is commutative + monotone, so
            // min over i!=j of (s_i+s_j) = m1+m2; max = M1+M2.
            float minsum = m1 + m2;       // -> end  (sig2 decreasing in sum)
            float maxsum = M1 + M2;       // -> begin
            float begin    = sig2_of_sum(maxsum);
            float end      = sig2_of_sum(minsum);
            float interval = (end - begin) / 10.0f;

            // Conservative sigma-sum threshold for bin-9 candidacy.
            // Need sig2 >= begin + 9*interval (float-rounding slack folded into
            // multiplicative margins). Invert via expm1 for precision.
            float th = (begin + 9.0f * interval) * 0.999f;
            float sigth;
            if (th > 0.0f && interval > 0.0f) {
                float u     = -expm1f(-2.0f / th);          // = 1 - exp(-2/th)
                float avg_b = sqrtf(fmaxf(u, 0.0f)) * 1.002f;
                float sum_b = avg_b * 200.0f + 0.01f;       // loose sum bound
                sigth = sum_b - m1;                          // per-index bound
            } else {
                sigth = FLT_MAX;  // degenerate: admit everything (slow but correct)
            }
            s_begin = begin; s_interval = interval; s_sigth = sigth;
            s_count = 0;
        }
    }
    __syncthreads();

    // ---- Phase B: gather candidate indices (sigma small enough) ----
    for (int i = tid; i < N; i += NTHREADS) {
        if (s_sig[i] <= s_sigth) {
            int p = atomicAdd(&s_count, 1);
            if (p < MAXN) s_cand[p] = i;
        }
    }
    __syncthreads();
    int K = s_count; if (K > MAXN) K = MAXN;
    // deterministic ordering for small K (normal case)
    if (tid == 0 && K > 1 && K <= 512) {
        for (int a = 1; a < K; a++) {
            int v = s_cand[a], b = a - 1;
            while (b >= 0 && s_cand[b] > v) { s_cand[b + 1] = s_cand[b]; b--; }
            s_cand[b + 1] = v;
        }
    }
    __syncthreads();

    // ---- Phase C: exact evaluation of candidate pairs ----
    const float begin    = s_begin;
    const float interval = s_interval;
    float cnt = 0.0f, ss = 0.0f, st = 0.0f;
    long total = (long)K * (long)K;
    for (long p = tid; p < total; p += NTHREADS) {
        int a = (int)(p / K);
        int b = (int)(p - (long)a * K);
        int i = s_cand[a], j = s_cand[b];
        if (i == j) continue;                    // off-diagonal only
        float s    = s_sig[i] + s_sig[j];
        float sig2 = sig2_of_sum(s);
        float t    = (sig2 - begin) / interval;
        int bi = (int)floorf(t);
        bi = bi < 0 ? 0 : (bi > 9 ? 9 : bi);
        if (bi == 9) {
            float dx = y[3*i]   - y[3*j];
            float dy = y[3*i+1] - y[3*j+1];
            float dz = y[3*i+2] - y[3*j+2];
            float dg = sqrtf(dx*dx + dy*dy + dz*dz);
            float ex = py[3*i]   - py[3*j];
            float ey = py[3*i+1] - py[3*j+1];
            float ez = py[3*i+2] - py[3*j+2];
            float dp = sqrtf(ex*ex + ey*ey + ez*ez);
            float tr = dg - dp;
            cnt += 1.0f;
            ss  += sig2;
            st  += tr * tr;
        }
    }
    // block reduce (deterministic tree)
    #pragma unroll
    for (int off = 16; off; off >>= 1) {
        cnt += __shfl_down_sync(FULL, cnt, off);
        ss  += __shfl_down_sync(FULL, ss,  off);
        st  += __shfl_down_sync(FULL, st,  off);
    }
    if ((tid & 31) == 0) { r_cnt[tid >> 5] = cnt; r_ss[tid >> 5] = ss; r_st[tid >> 5] = st; }
    __syncthreads();
    if (tid < 32) {
        cnt = r_cnt[tid]; ss = r_ss[tid]; st = r_st[tid];
        #pragma unroll
        for (int off = 16; off; off >>= 1) {
            cnt += __shfl_down_sync(FULL, cnt, off);
            ss  += __shfl_down_sync(FULL, ss,  off);
            st  += __shfl_down_sync(FULL, st,  off);
        }
        if (tid == 0) {
            float mvar = sqrtf(ss / cnt);   // cnt >= 2 always (end-pair is in bin 9)
            float rmse = sqrtf(st / cnt);
            out[0] = fabsf(mvar - rmse) / mvar;
        }
    }
}

extern "C" void kernel_launch(void* const* d_in, const int* in_sizes, int n_in,
                              void* d_out, int out_size) {
    const float* sigmas = (const float*)d_in[0];
    const float* y      = (const float*)d_in[1];
    const float* py     = (const float*)d_in[2];
    int N = in_sizes[0];
    ENCELDDT_67602785239182_kernel<<<1, NTHREADS>>>(sigmas, y, py, (float*)d_out, N);
}